// round 6
// baseline (speedup 1.0000x reference)
#include <cuda_runtime.h>

#define NN     100000
#define EDIM   128
#define QBLKS  256          // qmin partial blocks inside k0 (one partial each, no atomics)
#define K0PREP 16           // prep blocks (16 blocks * 8 warps = 128 j's)

// Persistent device scratch (no allocs in kernel_launch).
__device__ float  g_a[EDIM];
__device__ float  g_b[EDIM];
__device__ float  g_c[EDIM];
__device__ float2 g_T1[NN];                 // (s1, s1 + s3shift)
__device__ float2 g_T2[NN];                 // (s2 + bias, s2 + s3shift + bias)
__device__ int    g_partmin[QBLKS];         // per-block qmin partials (plain stores)

// ───────────── K0: blocks 0..15 fold Wo into Wq; blocks 16..271 qmin partials (int4)
__global__ void k0_prep_qmin(const float* __restrict__ Wq, const float* __restrict__ Wo,
                             const int* __restrict__ ei, int E) {
    int bid  = blockIdx.x;
    int warp = threadIdx.x >> 5;
    int lane = threadIdx.x & 31;

    if (bid < K0PREP) {
        int j = bid * 8 + warp;             // output column
        float b = 0.f, c = 0.f;
        #pragma unroll
        for (int k = 0; k < 4; k++) {
            int i = lane + 32 * k;
            float w = Wo[EDIM + i];
            b += w * Wq[i * 2 * EDIM + j];
            c += w * Wq[i * 2 * EDIM + EDIM + j];
        }
        #pragma unroll
        for (int o = 16; o; o >>= 1) {
            b += __shfl_xor_sync(0xffffffffu, b, o);
            c += __shfl_xor_sync(0xffffffffu, c, o);
        }
        if (lane == 0) {
            g_a[j] = Wo[j];
            g_b[j] = b;
            g_c[j] = c;
        }
    } else {
        // qmin partial sweep: ~4 int4-pairs per thread, one plain store per block.
        __shared__ int smin[8];
        int pb = bid - K0PREP;
        int E4 = E >> 2;
        const int4* s4p = (const int4*)ei;
        const int4* d4p = (const int4*)(ei + E);
        int local = 0x7fffffff;
        int stride = QBLKS * 256;
        for (int i = pb * 256 + threadIdx.x; i < E4; i += stride) {
            int4 s = s4p[i];
            int4 d = d4p[i];
            int m0 = max(s.x, d.x), m1 = max(s.y, d.y);
            int m2 = max(s.z, d.z), m3 = max(s.w, d.w);
            local = min(local, min(min(m0, m1), min(m2, m3)));
        }
        for (int e = (E4 << 2) + pb * 256 + threadIdx.x; e < E; e += stride)
            local = min(local, max(ei[e], ei[E + e]));
        #pragma unroll
        for (int o = 16; o; o >>= 1)
            local = min(local, __shfl_xor_sync(0xffffffffu, local, o));
        if (lane == 0) smin[warp] = local;
        __syncthreads();
        if (threadIdx.x == 0) {
            int v = smin[0];
            #pragma unroll
            for (int w = 1; w < 8; w++) v = min(v, smin[w]);
            g_partmin[pb] = v;               // distinct address per block — no contention
        }
    }
}

// ───────────── K2: node tables, 4 nodes per warp; warp 7 reduces qmin partials
__global__ void k2_nodes(const float* __restrict__ z, const float* __restrict__ z0,
                         const float* __restrict__ bo, int N) {
    __shared__ float sa[EDIM], sb[EDIM], sc[EDIM];
    __shared__ int   sqmin;
    int warp = threadIdx.x >> 5;
    int lane = threadIdx.x & 31;

    // threads 0..127 fill the weight vectors; warp 7 reduces the 256 qmin partials
    for (int i = threadIdx.x; i < EDIM; i += blockDim.x) {
        sa[i] = g_a[i]; sb[i] = g_b[i]; sc[i] = g_c[i];
    }
    if (warp == 7) {
        int v = min(g_partmin[lane], g_partmin[lane + 32]);
        #pragma unroll
        for (int t = 2; t < 8; t++) v = min(v, g_partmin[lane + 32 * t]);
        #pragma unroll
        for (int o = 16; o; o >>= 1)
            v = min(v, __shfl_xor_sync(0xffffffffu, v, o));
        if (lane == 0) sqmin = v;
    }
    __syncthreads();

    int node0 = (blockIdx.x * (blockDim.x >> 5) + warp) * 4;
    if (node0 >= N) return;

    int   qmin = sqmin;
    float bias = bo[0];
    int   k    = lane * 4;

    float4 vz[4], w4[4];
    bool   hasw[4];
    #pragma unroll
    for (int t = 0; t < 4; t++) {
        int node = node0 + t;
        int nc   = (node < N) ? node : (N - 1);
        vz[t] = ((const float4*)(z + (size_t)nc * EDIM))[lane];
        int m = nc - qmin;
        hasw[t] = (m >= 0);
        int mc = hasw[t] ? m : 0;
        w4[t] = ((const float4*)(z0 + (size_t)mc * EDIM))[lane];
    }
    #pragma unroll
    for (int t = 0; t < 4; t++) {
        int node = node0 + t;
        float s1 = vz[t].x * sa[k] + vz[t].y * sa[k+1] + vz[t].z * sa[k+2] + vz[t].w * sa[k+3];
        float s2 = vz[t].x * sb[k] + vz[t].y * sb[k+1] + vz[t].z * sb[k+2] + vz[t].w * sb[k+3];
        float s3 = hasw[t]
                 ? (w4[t].x * sc[k] + w4[t].y * sc[k+1] + w4[t].z * sc[k+2] + w4[t].w * sc[k+3])
                 : 0.f;
        #pragma unroll
        for (int o = 16; o; o >>= 1) {
            s1 += __shfl_xor_sync(0xffffffffu, s1, o);
            s2 += __shfl_xor_sync(0xffffffffu, s2, o);
            s3 += __shfl_xor_sync(0xffffffffu, s3, o);
        }
        if (lane == 0 && node < N) {
            g_T1[node] = make_float2(s1, s1 + s3);
            g_T2[node] = make_float2(s2 + bias, s2 + s3 + bias);
        }
    }
}

// ───────────── K3: per-edge output, 8 edges/thread (16 gathers in flight)
__global__ void k3_edges(const int* __restrict__ ei, float* __restrict__ out, int E) {
    int base = (blockIdx.x * blockDim.x + threadIdx.x) * 8;
    if (base + 7 < E) {
        int4 sA = *(const int4*)(ei + base);
        int4 sB = *(const int4*)(ei + base + 4);
        int4 dA = *(const int4*)(ei + E + base);
        int4 dB = *(const int4*)(ei + E + base + 4);
        int s[8] = { sA.x, sA.y, sA.z, sA.w, sB.x, sB.y, sB.z, sB.w };
        int d[8] = { dA.x, dA.y, dA.z, dA.w, dB.x, dB.y, dB.z, dB.w };
        float2 u[8], v[8];
        #pragma unroll
        for (int t = 0; t < 8; t++) u[t] = g_T1[s[t]];
        #pragma unroll
        for (int t = 0; t < 8; t++) v[t] = g_T2[d[t]];
        float r[8];
        #pragma unroll
        for (int t = 0; t < 8; t++)
            r[t] = (s[t] >= d[t]) ? (u[t].y + v[t].x) : (u[t].x + v[t].y);
        *(float4*)(out + base)     = make_float4(r[0], r[1], r[2], r[3]);
        *(float4*)(out + base + 4) = make_float4(r[4], r[5], r[6], r[7]);
    } else {
        for (int e = base; e < E; e++) {
            int ss = ei[e], dd = ei[E + e];
            float2 u = g_T1[ss];
            float2 v = g_T2[dd];
            out[e] = (ss >= dd) ? (u.y + v.x) : (u.x + v.y);
        }
    }
}

extern "C" void kernel_launch(void* const* d_in, const int* in_sizes, int n_in,
                              void* d_out, int out_size) {
    // Inputs (metadata order): z, edge_index, z0, Wq, Wo, bo
    const float* z  = (const float*)d_in[0];
    const int*   ei = (const int*)d_in[1];      // jax default int32
    const float* z0 = (const float*)d_in[2];
    const float* Wq = (const float*)d_in[3];
    const float* Wo = (const float*)d_in[4];
    const float* bo = (const float*)d_in[5];
    float* out = (float*)d_out;

    int N = in_sizes[0] / EDIM;     // 100000
    int E = in_sizes[1] / 2;        // 1000000

    k0_prep_qmin<<<K0PREP + QBLKS, 256>>>(Wq, Wo, ei, E);
    k2_nodes<<<(N + 31) / 32, 256>>>(z, z0, bo, N);
    int threads3 = (E + 7) / 8;
    k3_edges<<<(threads3 + 255) / 256, 256>>>(ei, out, E);
}